// round 7
// baseline (speedup 1.0000x reference)
#include <cuda_runtime.h>
#include <math.h>

#define BB   4
#define SS   2048
#define DIN  1024
#define NH   4          // kv heads
#define HD   64
#define NQ   256        // NH*HD
#define MR   (BB*SS)    // 8192 rows

// -------- scratch (device globals; no allocation allowed) --------
__device__ float g_WqEff[DIN * NQ];   // 1 MB
__device__ float g_Q [MR * NQ];       // 8 MB
__device__ float g_K [MR * NQ];       // 8 MB
__device__ float g_V [MR * NQ];       // 8 MB
__device__ float g_AO[MR * NQ];       // 8 MB

// ============================================================
// Wq group-sum: Wq[1024,16,64] -> Wq_eff[1024,4,64]
// head hq = h*4 + g ; Wq_eff[i,h,d] = sum_g Wq[i,h*4+g,d]
// ============================================================
__global__ void wq_reduce_kernel(const float* __restrict__ Wq) {
    int idx = blockIdx.x * blockDim.x + threadIdx.x;
    if (idx >= DIN * NQ) return;
    int i = idx >> 8;          // / 256
    int n = idx & 255;         // h*64+d
    int h = n >> 6, d = n & 63;
    const float* p = Wq + (size_t)i * 1024 + (h * 4) * 64 + d;
    g_WqEff[idx] = (p[0] + p[64]) + (p[128] + p[192]);
}

// ============================================================
// Generic row-major GEMM: C[M,N] = A[M,K] * B[K,N]
// 64x64 tile, BK=16, 256 threads, 4x4 micro-tile per thread.
// M,N multiples of 64; K multiple of 16.
// ============================================================
__global__ void __launch_bounds__(256)
gemm_kernel(const float* __restrict__ A, const float* __restrict__ Bm,
            float* __restrict__ C, int K, int N) {
    __shared__ float As[64][17];
    __shared__ float Bs[16][64];
    int tid = threadIdx.x;
    int tx = tid & 15, ty = tid >> 4;
    int bm = blockIdx.y << 6, bn = blockIdx.x << 6;

    int ar  = tid >> 2;          // 0..63
    int ac4 = (tid & 3) << 2;    // 0,4,8,12
    int br  = tid >> 4;          // 0..15
    int bc4 = (tid & 15) << 2;   // 0..60

    float acc[4][4] = {};

    for (int k0 = 0; k0 < K; k0 += 16) {
        float4 av = *reinterpret_cast<const float4*>(A + (size_t)(bm + ar) * K + k0 + ac4);
        As[ar][ac4 + 0] = av.x; As[ar][ac4 + 1] = av.y;
        As[ar][ac4 + 2] = av.z; As[ar][ac4 + 3] = av.w;
        float4 bv = *reinterpret_cast<const float4*>(Bm + (size_t)(k0 + br) * N + bn + bc4);
        *reinterpret_cast<float4*>(&Bs[br][bc4]) = bv;
        __syncthreads();

        #pragma unroll
        for (int kk = 0; kk < 16; kk++) {
            float a0 = As[(ty << 2) + 0][kk];
            float a1 = As[(ty << 2) + 1][kk];
            float a2 = As[(ty << 2) + 2][kk];
            float a3 = As[(ty << 2) + 3][kk];
            float4 b4 = *reinterpret_cast<float4*>(&Bs[kk][tx << 2]);
            acc[0][0] += a0 * b4.x; acc[0][1] += a0 * b4.y; acc[0][2] += a0 * b4.z; acc[0][3] += a0 * b4.w;
            acc[1][0] += a1 * b4.x; acc[1][1] += a1 * b4.y; acc[1][2] += a1 * b4.z; acc[1][3] += a1 * b4.w;
            acc[2][0] += a2 * b4.x; acc[2][1] += a2 * b4.y; acc[2][2] += a2 * b4.z; acc[2][3] += a2 * b4.w;
            acc[3][0] += a3 * b4.x; acc[3][1] += a3 * b4.y; acc[3][2] += a3 * b4.z; acc[3][3] += a3 * b4.w;
        }
        __syncthreads();
    }

    #pragma unroll
    for (int i = 0; i < 4; i++) {
        float4 o = make_float4(acc[i][0], acc[i][1], acc[i][2], acc[i][3]);
        *reinterpret_cast<float4*>(C + (size_t)(bm + (ty << 2) + i) * N + bn + (tx << 2)) = o;
    }
}

// ============================================================
// 2-axis RoPE in place on X[MR, NQ] (layout row=(b,s), col=h*64+d).
// Per head: 32 pairs. pair m: axis=m/16, freq j=m%16,
// angle = coord[axis] * 10000^(-j/16); rotate (x[2m], x[2m+1]).
// grid = MR rows, 128 threads (4 heads x 32 pairs).
// ============================================================
__global__ void rope_kernel(float* __restrict__ X, const int* __restrict__ coords) {
    int row = blockIdx.x;
    int t = threadIdx.x;       // 0..127
    int h = t >> 5;            // head 0..3
    int m = t & 31;            // pair 0..31
    int axis = m >> 4, j = m & 15;
    float c = (float)coords[(size_t)row * 2 + axis];
    // inv_freq computed in double then rounded to fp32 (matches jax fp32 value)
    float inv = (float)exp(-(double)j * (9.210340371976184 / 16.0)); // ln(10000)/16
    float ang = c * inv;       // fp32 multiply, same quantization as reference
    float sn, cs;
    sincosf(ang, &sn, &cs);
    float* p = X + (size_t)row * NQ + h * HD + 2 * m;
    float x1 = p[0], x2 = p[1];
    p[0] = x1 * cs - x2 * sn;
    p[1] = x1 * sn + x2 * cs;
}

// ============================================================
// Flash attention: per (b,h,qtile64). 256 threads, 4x4 micro.
// dyn smem: Q,K,V,P tiles 64x65 floats each = 66560 B.
// ============================================================
__global__ void __launch_bounds__(256)
attn_kernel() {
    extern __shared__ float sm[];
    float* Qs = sm;
    float* Ks = sm + 64 * 65;
    float* Vs = sm + 2 * 64 * 65;
    float* Ps = sm + 3 * 64 * 65;

    int bid = blockIdx.x;
    int mt = bid & 31;         // q tile
    int bh = bid >> 5;         // 0..15
    int h = bh & 3, b = bh >> 2;

    int tid = threadIdx.x;
    int tx = tid & 15, ty = tid >> 4;

    const float* Qg = g_Q + (size_t)b * SS * NQ + h * HD;
    const float* Kg = g_K + (size_t)b * SS * NQ + h * HD;
    const float* Vg = g_V + (size_t)b * SS * NQ + h * HD;

    int s0 = mt << 6;

    // load Q tile [64][64]
    for (int idx = tid; idx < 1024; idx += 256) {
        int r = idx >> 4, c4 = (idx & 15) << 2;
        float4 v = *reinterpret_cast<const float4*>(Qg + (size_t)(s0 + r) * NQ + c4);
        Qs[r * 65 + c4 + 0] = v.x; Qs[r * 65 + c4 + 1] = v.y;
        Qs[r * 65 + c4 + 2] = v.z; Qs[r * 65 + c4 + 3] = v.w;
    }

    float mi[4] = {-1e30f, -1e30f, -1e30f, -1e30f};
    float li[4] = {0.f, 0.f, 0.f, 0.f};
    float O[4][4] = {};

    for (int nt = 0; nt < 32; nt++) {
        __syncthreads();   // protect K/V/P from previous iter's readers
        int kb = nt << 6;
        for (int idx = tid; idx < 1024; idx += 256) {
            int r = idx >> 4, c4 = (idx & 15) << 2;
            float4 kv = *reinterpret_cast<const float4*>(Kg + (size_t)(kb + r) * NQ + c4);
            Ks[r * 65 + c4 + 0] = kv.x; Ks[r * 65 + c4 + 1] = kv.y;
            Ks[r * 65 + c4 + 2] = kv.z; Ks[r * 65 + c4 + 3] = kv.w;
            float4 vv = *reinterpret_cast<const float4*>(Vg + (size_t)(kb + r) * NQ + c4);
            Vs[r * 65 + c4 + 0] = vv.x; Vs[r * 65 + c4 + 1] = vv.y;
            Vs[r * 65 + c4 + 2] = vv.z; Vs[r * 65 + c4 + 3] = vv.w;
        }
        __syncthreads();

        // S = Q K^T (4x4 per thread)
        float acc[4][4] = {};
        #pragma unroll 8
        for (int d = 0; d < 64; d++) {
            float q0 = Qs[((ty << 2) + 0) * 65 + d];
            float q1 = Qs[((ty << 2) + 1) * 65 + d];
            float q2 = Qs[((ty << 2) + 2) * 65 + d];
            float q3 = Qs[((ty << 2) + 3) * 65 + d];
            float k0 = Ks[((tx << 2) + 0) * 65 + d];
            float k1 = Ks[((tx << 2) + 1) * 65 + d];
            float k2 = Ks[((tx << 2) + 2) * 65 + d];
            float k3 = Ks[((tx << 2) + 3) * 65 + d];
            acc[0][0] += q0 * k0; acc[0][1] += q0 * k1; acc[0][2] += q0 * k2; acc[0][3] += q0 * k3;
            acc[1][0] += q1 * k0; acc[1][1] += q1 * k1; acc[1][2] += q1 * k2; acc[1][3] += q1 * k3;
            acc[2][0] += q2 * k0; acc[2][1] += q2 * k1; acc[2][2] += q2 * k2; acc[2][3] += q2 * k3;
            acc[3][0] += q3 * k0; acc[3][1] += q3 * k1; acc[3][2] += q3 * k2; acc[3][3] += q3 * k3;
        }

        // online softmax per row (reduce across the 16 tx lanes; xor<=8 stays in half-warp)
        #pragma unroll
        for (int i = 0; i < 4; i++) {
            float r0 = acc[i][0] * 0.125f;
            float r1 = acc[i][1] * 0.125f;
            float r2 = acc[i][2] * 0.125f;
            float r3 = acc[i][3] * 0.125f;
            float rmax = fmaxf(fmaxf(r0, r1), fmaxf(r2, r3));
            #pragma unroll
            for (int o = 8; o >= 1; o >>= 1)
                rmax = fmaxf(rmax, __shfl_xor_sync(0xffffffffu, rmax, o));
            float mnew = fmaxf(mi[i], rmax);
            float corr = __expf(mi[i] - mnew);
            float p0 = __expf(r0 - mnew);
            float p1 = __expf(r1 - mnew);
            float p2 = __expf(r2 - mnew);
            float p3 = __expf(r3 - mnew);
            float* pr = Ps + ((ty << 2) + i) * 65 + (tx << 2);
            pr[0] = p0; pr[1] = p1; pr[2] = p2; pr[3] = p3;
            float rsum = (p0 + p1) + (p2 + p3);
            #pragma unroll
            for (int o = 8; o >= 1; o >>= 1)
                rsum += __shfl_xor_sync(0xffffffffu, rsum, o);
            li[i] = li[i] * corr + rsum;
            mi[i] = mnew;
            O[i][0] *= corr; O[i][1] *= corr; O[i][2] *= corr; O[i][3] *= corr;
        }
        __syncthreads();   // P fully written before PV

        // O += P @ V
        #pragma unroll 8
        for (int n = 0; n < 64; n++) {
            float p0 = Ps[((ty << 2) + 0) * 65 + n];
            float p1 = Ps[((ty << 2) + 1) * 65 + n];
            float p2 = Ps[((ty << 2) + 2) * 65 + n];
            float p3 = Ps[((ty << 2) + 3) * 65 + n];
            float v0 = Vs[n * 65 + (tx << 2) + 0];
            float v1 = Vs[n * 65 + (tx << 2) + 1];
            float v2 = Vs[n * 65 + (tx << 2) + 2];
            float v3 = Vs[n * 65 + (tx << 2) + 3];
            O[0][0] += p0 * v0; O[0][1] += p0 * v1; O[0][2] += p0 * v2; O[0][3] += p0 * v3;
            O[1][0] += p1 * v0; O[1][1] += p1 * v1; O[1][2] += p1 * v2; O[1][3] += p1 * v3;
            O[2][0] += p2 * v0; O[2][1] += p2 * v1; O[2][2] += p2 * v2; O[2][3] += p2 * v3;
            O[3][0] += p3 * v0; O[3][1] += p3 * v1; O[3][2] += p3 * v2; O[3][3] += p3 * v3;
        }
    }

    float* Og = g_AO + (size_t)b * SS * NQ + h * HD;
    #pragma unroll
    for (int i = 0; i < 4; i++) {
        float inv = 1.0f / li[i];
        float4 o = make_float4(O[i][0] * inv, O[i][1] * inv, O[i][2] * inv, O[i][3] * inv);
        *reinterpret_cast<float4*>(Og + (size_t)(s0 + (ty << 2) + i) * NQ + (tx << 2)) = o;
    }
}

// ============================================================
// launch
// ============================================================
extern "C" void kernel_launch(void* const* d_in, const int* in_sizes, int n_in,
                              void* d_out, int out_size) {
    (void)in_sizes; (void)n_in; (void)out_size;
    const float* q  = (const float*)d_in[0];
    const int*   qc = (const int*)  d_in[1];
    const float* kv = (const float*)d_in[2];
    const int*   kc = (const int*)  d_in[3];
    const float* Wq = (const float*)d_in[4];
    const float* Wk = (const float*)d_in[5];
    const float* Wv = (const float*)d_in[6];
    const float* Wo = (const float*)d_in[7];
    float* out = (float*)d_out;

    cudaFuncSetAttribute(attn_kernel, cudaFuncAttributeMaxDynamicSharedMemorySize, 66560);

    void *pWqEff, *pQ, *pK, *pV, *pAO;
    cudaGetSymbolAddress(&pWqEff, g_WqEff);
    cudaGetSymbolAddress(&pQ,  g_Q);
    cudaGetSymbolAddress(&pK,  g_K);
    cudaGetSymbolAddress(&pV,  g_V);
    cudaGetSymbolAddress(&pAO, g_AO);

    // 1. Wq group-sum
    wq_reduce_kernel<<<(DIN * NQ) / 256, 256>>>(Wq);

    // 2. projections: [8192,1024] x [1024,256]
    dim3 gproj(NQ / 64, MR / 64);
    gemm_kernel<<<gproj, 256>>>(q,  (const float*)pWqEff, (float*)pQ, DIN, NQ);
    gemm_kernel<<<gproj, 256>>>(kv, Wk,                   (float*)pK, DIN, NQ);
    gemm_kernel<<<gproj, 256>>>(kv, Wv,                   (float*)pV, DIN, NQ);

    // 3. RoPE in place on Q_eff and K
    rope_kernel<<<MR, 128>>>((float*)pQ, qc);
    rope_kernel<<<MR, 128>>>((float*)pK, kc);

    // 4. attention: 16 (b,h) x 32 q-tiles
    attn_kernel<<<16 * 32, 256, 66560>>>();

    // 5. output projection: [8192,256] x [256,1024]
    dim3 gout(DIN / 64, MR / 64);
    gemm_kernel<<<gout, 256>>>((const float*)pAO, Wo, out, NQ, DIN);
}